// round 1
// baseline (speedup 1.0000x reference)
#include <cuda_runtime.h>
#include <cuda_bf16.h>
#include <math.h>

// Problem constants
#define BATCH 4
#define SEQ   2048
#define EMBED 1024
#define HEADS 16
#define DH    64
#define BH    (BATCH*HEADS)   // 64

// Scratch: Q,K,V in [bh][s][d] layout + per-column softmax stats.
__device__ float g_Q[(size_t)BH*SEQ*DH];
__device__ float g_K[(size_t)BH*SEQ*DH];
__device__ float g_V[(size_t)BH*SEQ*DH];
__device__ float g_M [(size_t)BH*SEQ];
__device__ float g_IC[(size_t)BH*SEQ];

// ---------------------------------------------------------------------------
// Pass A: y = x @ W^T + bias  (M=8192, N=1024, K=1024), output remapped to
// [b][h][s][d] (h = n/64, d = n%64).  128x128x8 tile, 256 threads, 8x8 micro.
// ---------------------------------------------------------------------------
__global__ __launch_bounds__(256) void proj_kernel(
    const float* __restrict__ x, const float* __restrict__ W,
    const float* __restrict__ bias, float* __restrict__ outp)
{
    __shared__ float As[8][128];
    __shared__ float Bs[8][128];
    const int tid = threadIdx.x;
    const int m0 = blockIdx.y * 128;
    const int n0 = blockIdx.x * 128;
    const int lr = tid >> 1;           // 0..127
    const int lc = (tid & 1) * 4;      // 0 or 4
    const int tx = tid & 15;
    const int ty = tid >> 4;

    float acc[8][8];
#pragma unroll
    for (int i = 0; i < 8; i++)
#pragma unroll
        for (int j = 0; j < 8; j++) acc[i][j] = 0.f;

    const float* xA = x + (size_t)m0 * EMBED;
    const float* wB = W + (size_t)n0 * EMBED;

    for (int k0 = 0; k0 < EMBED; k0 += 8) {
        float4 av = *(const float4*)(xA + (size_t)lr * EMBED + k0 + lc);
        float4 bv = *(const float4*)(wB + (size_t)lr * EMBED + k0 + lc);
        As[lc + 0][lr] = av.x; As[lc + 1][lr] = av.y;
        As[lc + 2][lr] = av.z; As[lc + 3][lr] = av.w;
        Bs[lc + 0][lr] = bv.x; Bs[lc + 1][lr] = bv.y;
        Bs[lc + 2][lr] = bv.z; Bs[lc + 3][lr] = bv.w;
        __syncthreads();
#pragma unroll
        for (int kk = 0; kk < 8; kk++) {
            float a[8], b[8];
#pragma unroll
            for (int i = 0; i < 8; i++) a[i] = As[kk][ty * 8 + i];
#pragma unroll
            for (int j = 0; j < 8; j++) b[j] = Bs[kk][tx * 8 + j];
#pragma unroll
            for (int i = 0; i < 8; i++)
#pragma unroll
                for (int j = 0; j < 8; j++) acc[i][j] += a[i] * b[j];
        }
        __syncthreads();
    }

#pragma unroll
    for (int i = 0; i < 8; i++) {
        int m = m0 + ty * 8 + i;
        int b = m >> 11, s = m & 2047;
#pragma unroll
        for (int j = 0; j < 8; j++) {
            int n = n0 + tx * 8 + j;
            int h = n >> 6, d = n & 63;
            outp[(((size_t)(b * HEADS + h)) * SEQ + s) * DH + d] = acc[i][j] + bias[n];
        }
    }
}

// ---------------------------------------------------------------------------
// Pass B: per (bh, k): m_k = max_q S[q,k], den_k = sum_q exp(S-m_k).
// S[q,k] = dot64(Q[q], K[k]) * 0.1. CTA handles 64 k-columns, streams q.
// ---------------------------------------------------------------------------
__global__ __launch_bounds__(256) void stats_kernel(
    float* __restrict__ gM, float* __restrict__ gIC)
{
    __shared__ float Ks[64][65];
    __shared__ float Qs[64][65];
    __shared__ float redm[64][16];
    __shared__ float redd[64][16];
    const int tid = threadIdx.x;
    const int bh = blockIdx.y;
    const int k0 = blockIdx.x * 64;

    const float* Kp = g_K + ((size_t)bh * SEQ + k0) * DH;
    for (int i = tid; i < 64 * 16; i += 256) {
        int row = i >> 4, c4 = (i & 15) << 2;
        float4 v = *(const float4*)(Kp + (size_t)row * DH + c4);
        Ks[row][c4 + 0] = v.x; Ks[row][c4 + 1] = v.y;
        Ks[row][c4 + 2] = v.z; Ks[row][c4 + 3] = v.w;
    }
    const float* Qp = g_Q + (size_t)bh * SEQ * DH;
    const int tx = tid & 15, ty = tid >> 4;
    const int c0 = tx * 4, r0 = ty * 4;

    float rm[4], rd[4];
#pragma unroll
    for (int c = 0; c < 4; c++) { rm[c] = -1e30f; rd[c] = 0.f; }

    for (int q0 = 0; q0 < SEQ; q0 += 64) {
        __syncthreads();
        for (int i = tid; i < 64 * 16; i += 256) {
            int row = i >> 4, c4 = (i & 15) << 2;
            float4 v = *(const float4*)(Qp + (size_t)(q0 + row) * DH + c4);
            Qs[row][c4 + 0] = v.x; Qs[row][c4 + 1] = v.y;
            Qs[row][c4 + 2] = v.z; Qs[row][c4 + 3] = v.w;
        }
        __syncthreads();

        float s[4][4];
#pragma unroll
        for (int r = 0; r < 4; r++)
#pragma unroll
            for (int c = 0; c < 4; c++) s[r][c] = 0.f;
#pragma unroll 8
        for (int d = 0; d < DH; d++) {
            float kv[4], qv[4];
#pragma unroll
            for (int c = 0; c < 4; c++) kv[c] = Ks[c0 + c][d];
#pragma unroll
            for (int r = 0; r < 4; r++) qv[r] = Qs[r0 + r][d];
#pragma unroll
            for (int r = 0; r < 4; r++)
#pragma unroll
                for (int c = 0; c < 4; c++) s[r][c] += qv[r] * kv[c];
        }
#pragma unroll
        for (int c = 0; c < 4; c++) {
            float tm = fmaxf(fmaxf(s[0][c], s[1][c]), fmaxf(s[2][c], s[3][c])) * 0.1f;
            if (tm > rm[c]) { rd[c] *= __expf(rm[c] - tm); rm[c] = tm; }
#pragma unroll
            for (int r = 0; r < 4; r++) rd[c] += __expf(s[r][c] * 0.1f - rm[c]);
        }
    }

#pragma unroll
    for (int c = 0; c < 4; c++) { redm[c0 + c][ty] = rm[c]; redd[c0 + c][ty] = rd[c]; }
    __syncthreads();
    if (tid < 64) {
        float M = -1e30f;
#pragma unroll
        for (int i = 0; i < 16; i++) M = fmaxf(M, redm[tid][i]);
        float D = 0.f;
#pragma unroll
        for (int i = 0; i < 16; i++) D += redd[tid][i] * __expf(redm[tid][i] - M);
        gM [(size_t)bh * SEQ + k0 + tid] = M;
        gIC[(size_t)bh * SEQ + k0 + tid] = 1.0f / D;
    }
}

// ---------------------------------------------------------------------------
// Pass C: O[q,d] = sum_k exp(S[q,k]-m_k) * (V[k,d]*inv_den_k).
// CTA per (bh, 64-row q block); loops k tiles of 64; S recomputed per tile.
// ---------------------------------------------------------------------------
__global__ __launch_bounds__(256) void attn_kernel(
    float* __restrict__ out,
    const float* __restrict__ gM, const float* __restrict__ gIC)
{
    extern __shared__ float sm[];
    float (*Qs)[65] = (float (*)[65])(sm);
    float (*Ks)[65] = (float (*)[65])(sm + 4160);
    float (*Vs)[65] = (float (*)[65])(sm + 8320);
    float (*Es)[65] = (float (*)[65])(sm + 12480);
    float* mv = sm + 16640;

    const int tid = threadIdx.x;
    const int bh = blockIdx.y;
    const int q0 = blockIdx.x * 64;

    const float* Qp = g_Q + ((size_t)bh * SEQ + q0) * DH;
    for (int i = tid; i < 64 * 16; i += 256) {
        int row = i >> 4, c4 = (i & 15) << 2;
        float4 v = *(const float4*)(Qp + (size_t)row * DH + c4);
        Qs[row][c4 + 0] = v.x; Qs[row][c4 + 1] = v.y;
        Qs[row][c4 + 2] = v.z; Qs[row][c4 + 3] = v.w;
    }
    const int tx = tid & 15, ty = tid >> 4;
    const int c0 = tx * 4, r0 = ty * 4;

    float o[4][4];
#pragma unroll
    for (int r = 0; r < 4; r++)
#pragma unroll
        for (int c = 0; c < 4; c++) o[r][c] = 0.f;

    for (int k0 = 0; k0 < SEQ; k0 += 64) {
        __syncthreads();   // protects Qs (first iter) and Ks/Vs/Es reuse
        const float* Kp  = g_K + ((size_t)bh * SEQ + k0) * DH;
        const float* Vp  = g_V + ((size_t)bh * SEQ + k0) * DH;
        const float* icp = gIC + (size_t)bh * SEQ + k0;
        for (int i = tid; i < 64 * 16; i += 256) {
            int row = i >> 4, c4 = (i & 15) << 2;
            float4 v = *(const float4*)(Kp + (size_t)row * DH + c4);
            Ks[row][c4 + 0] = v.x; Ks[row][c4 + 1] = v.y;
            Ks[row][c4 + 2] = v.z; Ks[row][c4 + 3] = v.w;
            float ic = icp[row];
            float4 w = *(const float4*)(Vp + (size_t)row * DH + c4);
            Vs[row][c4 + 0] = w.x * ic; Vs[row][c4 + 1] = w.y * ic;
            Vs[row][c4 + 2] = w.z * ic; Vs[row][c4 + 3] = w.w * ic;
        }
        if (tid < 64) mv[tid] = gM[(size_t)bh * SEQ + k0 + tid];
        __syncthreads();

        // S tile: rows = q (r0), cols = k (c0)
        float s[4][4];
#pragma unroll
        for (int r = 0; r < 4; r++)
#pragma unroll
            for (int c = 0; c < 4; c++) s[r][c] = 0.f;
#pragma unroll 8
        for (int d = 0; d < DH; d++) {
            float kv[4], qv[4];
#pragma unroll
            for (int c = 0; c < 4; c++) kv[c] = Ks[c0 + c][d];
#pragma unroll
            for (int r = 0; r < 4; r++) qv[r] = Qs[r0 + r][d];
#pragma unroll
            for (int r = 0; r < 4; r++)
#pragma unroll
                for (int c = 0; c < 4; c++) s[r][c] += qv[r] * kv[c];
        }
#pragma unroll
        for (int r = 0; r < 4; r++)
#pragma unroll
            for (int c = 0; c < 4; c++)
                Es[r0 + r][c0 + c] = __expf(s[r][c] * 0.1f - mv[c0 + c]);
        __syncthreads();

        // O tile: rows = q (r0), cols = d (c0); reduce over k
#pragma unroll 8
        for (int k = 0; k < 64; k++) {
            float ev[4], vv[4];
#pragma unroll
            for (int r = 0; r < 4; r++) ev[r] = Es[r0 + r][k];
#pragma unroll
            for (int c = 0; c < 4; c++) vv[c] = Vs[k][c0 + c];
#pragma unroll
            for (int r = 0; r < 4; r++)
#pragma unroll
                for (int c = 0; c < 4; c++) o[r][c] += ev[r] * vv[c];
        }
    }

    const int b = bh >> 4, h = bh & 15;
#pragma unroll
    for (int r = 0; r < 4; r++) {
        int q = q0 + r0 + r;
        float4 v = make_float4(o[r][0], o[r][1], o[r][2], o[r][3]);
        *(float4*)(out + ((size_t)(b * SEQ + q)) * EMBED + h * DH + c0) = v;
    }
}

// ---------------------------------------------------------------------------
extern "C" void kernel_launch(void* const* d_in, const int* in_sizes, int n_in,
                              void* d_out, int out_size)
{
    const float* x  = (const float*)d_in[0];
    const float* Wq = (const float*)d_in[1];
    const float* bq = (const float*)d_in[2];
    const float* Wk = (const float*)d_in[3];
    const float* bk = (const float*)d_in[4];
    const float* Wv = (const float*)d_in[5];
    const float* bv = (const float*)d_in[6];
    float* out = (float*)d_out;

    float *pQ, *pK, *pV, *pM, *pIC;
    cudaGetSymbolAddress((void**)&pQ,  g_Q);
    cudaGetSymbolAddress((void**)&pK,  g_K);
    cudaGetSymbolAddress((void**)&pV,  g_V);
    cudaGetSymbolAddress((void**)&pM,  g_M);
    cudaGetSymbolAddress((void**)&pIC, g_IC);

    dim3 pg(EMBED / 128, (BATCH * SEQ) / 128);   // (8, 64)
    proj_kernel<<<pg, 256>>>(x, Wq, bq, pQ);
    proj_kernel<<<pg, 256>>>(x, Wk, bk, pK);
    proj_kernel<<<pg, 256>>>(x, Wv, bv, pV);

    dim3 sg(SEQ / 64, BH);                        // (32, 64)
    stats_kernel<<<sg, 256>>>(pM, pIC);

    const int attn_smem = (4 * 4160 + 64) * (int)sizeof(float);  // 66816 B
    cudaFuncSetAttribute(attn_kernel, cudaFuncAttributeMaxDynamicSharedMemorySize, attn_smem);
    attn_kernel<<<sg, 256, attn_smem>>>(out, pM, pIC);
}

// round 2
// speedup vs baseline: 1.0662x; 1.0662x over previous
#include <cuda_runtime.h>
#include <cuda_bf16.h>
#include <math.h>

#define BATCH 4
#define SEQ   2048
#define EMBED 1024
#define HEADS 16
#define DH    64
#define BH    (BATCH*HEADS)   // 64

// Scratch: Q,K,V in [bh][s][d] layout + per-column softmax stats.
__device__ float g_Q[(size_t)BH*SEQ*DH];
__device__ float g_K[(size_t)BH*SEQ*DH];
__device__ float g_V[(size_t)BH*SEQ*DH];
__device__ float g_M [(size_t)BH*SEQ];
__device__ float g_IC[(size_t)BH*SEQ];

// ---------------------------------------------------------------------------
// Pass A: y = x @ W^T + bias (M=8192, N=1024, K=1024) -> [b][h][s][d].
// 128x128 tile, k-chunk 16, 256 threads, 8x8 micro.
// ---------------------------------------------------------------------------
__global__ __launch_bounds__(256) void proj_kernel(
    const float* __restrict__ x, const float* __restrict__ W,
    const float* __restrict__ bias, float* __restrict__ outp)
{
    __shared__ float As[16][128];
    __shared__ float Bs[16][128];
    const int tid = threadIdx.x;
    const int m0 = blockIdx.y * 128;
    const int n0 = blockIdx.x * 128;
    const int tx = tid & 15;
    const int ty = tid >> 4;

    float acc[8][8];
#pragma unroll
    for (int i = 0; i < 8; i++)
#pragma unroll
        for (int j = 0; j < 8; j++) acc[i][j] = 0.f;

    const float* xA = x + (size_t)m0 * EMBED;
    const float* wB = W + (size_t)n0 * EMBED;

    for (int k0 = 0; k0 < EMBED; k0 += 16) {
#pragma unroll
        for (int u = 0; u < 2; u++) {
            int f = tid + u * 256;           // 0..511 float4 slots
            int row = f >> 2;
            int kc  = (f & 3) << 2;
            float4 av = *(const float4*)(xA + (size_t)row * EMBED + k0 + kc);
            float4 bv = *(const float4*)(wB + (size_t)row * EMBED + k0 + kc);
            As[kc + 0][row] = av.x; As[kc + 1][row] = av.y;
            As[kc + 2][row] = av.z; As[kc + 3][row] = av.w;
            Bs[kc + 0][row] = bv.x; Bs[kc + 1][row] = bv.y;
            Bs[kc + 2][row] = bv.z; Bs[kc + 3][row] = bv.w;
        }
        __syncthreads();
#pragma unroll
        for (int kk = 0; kk < 16; kk++) {
            float a[8], b[8];
#pragma unroll
            for (int i = 0; i < 8; i++) a[i] = As[kk][ty * 8 + i];
#pragma unroll
            for (int j = 0; j < 8; j++) b[j] = Bs[kk][tx * 8 + j];
#pragma unroll
            for (int i = 0; i < 8; i++)
#pragma unroll
                for (int j = 0; j < 8; j++) acc[i][j] += a[i] * b[j];
        }
        __syncthreads();
    }

#pragma unroll
    for (int i = 0; i < 8; i++) {
        int m = m0 + ty * 8 + i;
        int b = m >> 11, s = m & 2047;
#pragma unroll
        for (int j = 0; j < 8; j++) {
            int n = n0 + tx * 8 + j;
            int h = n >> 6, d = n & 63;
            outp[(((size_t)(b * HEADS + h)) * SEQ + s) * DH + d] = acc[i][j] + bias[n];
        }
    }
}

// ---------------------------------------------------------------------------
// Pass B: per (bh, k): m_k = max_q S, den_k = sum_q exp(S-m_k).
// 128 k-cols per CTA, q streamed in 128 chunks, 8x8 micro, d-major smem.
// ---------------------------------------------------------------------------
#define KT_S 132   // transposed tile row stride (floats), 16B-aligned
__global__ __launch_bounds__(256, 2) void stats_kernel(
    float* __restrict__ gM, float* __restrict__ gIC)
{
    extern __shared__ float sm[];
    float* Ks   = sm;                       // [64][KT_S]  (d-major)
    float* Qs   = sm + 64 * KT_S;           // [64][KT_S]
    float* redm = sm + 2 * 64 * KT_S;       // [128][16]
    float* redd = redm + 128 * 16;

    const int tid = threadIdx.x;
    const int bh = blockIdx.y;
    const int k0 = blockIdx.x * 128;
    const int tx = tid & 15, ty = tid >> 4;
    const int c0 = tx * 8, r0 = ty * 8;

    const float* Kp = g_K + ((size_t)bh * SEQ + k0) * DH;
    for (int i = tid; i < 128 * 16; i += 256) {
        int row = i >> 4, c4 = (i & 15) << 2;
        float4 v = *(const float4*)(Kp + (size_t)row * DH + c4);
        Ks[(c4 + 0) * KT_S + row] = v.x; Ks[(c4 + 1) * KT_S + row] = v.y;
        Ks[(c4 + 2) * KT_S + row] = v.z; Ks[(c4 + 3) * KT_S + row] = v.w;
    }
    const float* Qp = g_Q + (size_t)bh * SEQ * DH;

    float rm[8], rd[8];
#pragma unroll
    for (int c = 0; c < 8; c++) { rm[c] = -1e30f; rd[c] = 0.f; }

    for (int q0 = 0; q0 < SEQ; q0 += 128) {
        __syncthreads();
        for (int i = tid; i < 128 * 16; i += 256) {
            int row = i >> 4, c4 = (i & 15) << 2;
            float4 v = *(const float4*)(Qp + (size_t)(q0 + row) * DH + c4);
            Qs[(c4 + 0) * KT_S + row] = v.x; Qs[(c4 + 1) * KT_S + row] = v.y;
            Qs[(c4 + 2) * KT_S + row] = v.z; Qs[(c4 + 3) * KT_S + row] = v.w;
        }
        __syncthreads();

        float acc[8][8];
#pragma unroll
        for (int r = 0; r < 8; r++)
#pragma unroll
            for (int c = 0; c < 8; c++) acc[r][c] = 0.f;

#pragma unroll 8
        for (int d = 0; d < DH; d++) {
            float a[8], b[8];
            *(float4*)&a[0] = *(const float4*)&Qs[d * KT_S + r0];
            *(float4*)&a[4] = *(const float4*)&Qs[d * KT_S + r0 + 4];
            *(float4*)&b[0] = *(const float4*)&Ks[d * KT_S + c0];
            *(float4*)&b[4] = *(const float4*)&Ks[d * KT_S + c0 + 4];
#pragma unroll
            for (int r = 0; r < 8; r++)
#pragma unroll
                for (int c = 0; c < 8; c++) acc[r][c] += a[r] * b[c];
        }

#pragma unroll
        for (int c = 0; c < 8; c++) {
            float tm = acc[0][c];
#pragma unroll
            for (int r = 1; r < 8; r++) tm = fmaxf(tm, acc[r][c]);
            tm *= 0.1f;
            if (tm > rm[c]) { rd[c] *= __expf(rm[c] - tm); rm[c] = tm; }
#pragma unroll
            for (int r = 0; r < 8; r++) rd[c] += __expf(acc[r][c] * 0.1f - rm[c]);
        }
    }

#pragma unroll
    for (int c = 0; c < 8; c++) {
        redm[(c0 + c) * 16 + ty] = rm[c];
        redd[(c0 + c) * 16 + ty] = rd[c];
    }
    __syncthreads();
    if (tid < 128) {
        float M = -1e30f;
#pragma unroll
        for (int i = 0; i < 16; i++) M = fmaxf(M, redm[tid * 16 + i]);
        float D = 0.f;
#pragma unroll
        for (int i = 0; i < 16; i++) D += redd[tid * 16 + i] * __expf(redm[tid * 16 + i] - M);
        gM [(size_t)bh * SEQ + k0 + tid] = M;
        gIC[(size_t)bh * SEQ + k0 + tid] = 1.0f / D;
    }
}

// ---------------------------------------------------------------------------
// Pass C: O[q,d] = sum_k exp(S-m_k) * (V[k,d]/den_k).
// 64 q-rows per CTA, k tiled by 128. S: 4x8 micro (d-major smem).
// E stored row-major [q][k] aliased over the K tile; PV: 4x4 micro, k blocked
// by 4 so E reads are LDS.128.
// ---------------------------------------------------------------------------
#define QT_S 68    // Q / V tile row stride (floats)
__global__ __launch_bounds__(256, 2) void attn_kernel(
    float* __restrict__ out,
    const float* __restrict__ gM, const float* __restrict__ gIC)
{
    extern __shared__ float sm[];
    float* Qs = sm;                          // [64][QT_S]  d-major: Qs[d*QT_S+q]
    float* KE = sm + 64 * QT_S;              // Ks_t[d*KT_S+k] (8448) / Es[q*KT_S+k]
    float* Vs = KE + 64 * KT_S;              // [128][QT_S]  k-major: Vs[k*QT_S+d]
    float* mv = Vs + 128 * QT_S;             // [128]

    const int tid = threadIdx.x;
    const int bh = blockIdx.y;
    const int q0 = blockIdx.x * 64;
    const int tx = tid & 15, ty = tid >> 4;
    const int cs0 = tx * 8;                  // S-phase: 8 k-cols
    const int rq0 = ty * 4;                  // 4 q-rows (both phases)
    const int cp0 = tx * 4;                  // PV-phase: 4 d-cols

    const float* Qp = g_Q + ((size_t)bh * SEQ + q0) * DH;
    for (int i = tid; i < 64 * 16; i += 256) {
        int row = i >> 4, c4 = (i & 15) << 2;
        float4 v = *(const float4*)(Qp + (size_t)row * DH + c4);
        Qs[(c4 + 0) * QT_S + row] = v.x; Qs[(c4 + 1) * QT_S + row] = v.y;
        Qs[(c4 + 2) * QT_S + row] = v.z; Qs[(c4 + 3) * QT_S + row] = v.w;
    }

    float o[4][4];
#pragma unroll
    for (int r = 0; r < 4; r++)
#pragma unroll
        for (int c = 0; c < 4; c++) o[r][c] = 0.f;

    for (int k0 = 0; k0 < SEQ; k0 += 128) {
        __syncthreads();   // prior PV done with KE/Vs; also covers initial Qs
        const float* Kp  = g_K + ((size_t)bh * SEQ + k0) * DH;
        const float* Vp  = g_V + ((size_t)bh * SEQ + k0) * DH;
        const float* icp = gIC + (size_t)bh * SEQ + k0;
        for (int i = tid; i < 128 * 16; i += 256) {
            int row = i >> 4, c4 = (i & 15) << 2;
            float4 kv = *(const float4*)(Kp + (size_t)row * DH + c4);
            KE[(c4 + 0) * KT_S + row] = kv.x; KE[(c4 + 1) * KT_S + row] = kv.y;
            KE[(c4 + 2) * KT_S + row] = kv.z; KE[(c4 + 3) * KT_S + row] = kv.w;
            float ic = icp[row];
            float4 vv = *(const float4*)(Vp + (size_t)row * DH + c4);
            *(float4*)&Vs[row * QT_S + c4] =
                make_float4(vv.x * ic, vv.y * ic, vv.z * ic, vv.w * ic);
        }
        if (tid < 128) mv[tid] = gM[(size_t)bh * SEQ + k0 + tid];
        __syncthreads();

        // S tile: 4 q x 8 k per thread
        float s[4][8];
#pragma unroll
        for (int r = 0; r < 4; r++)
#pragma unroll
            for (int c = 0; c < 8; c++) s[r][c] = 0.f;
#pragma unroll 8
        for (int d = 0; d < DH; d++) {
            float a[4], b[8];
            *(float4*)&a[0] = *(const float4*)&Qs[d * QT_S + rq0];
            *(float4*)&b[0] = *(const float4*)&KE[d * KT_S + cs0];
            *(float4*)&b[4] = *(const float4*)&KE[d * KT_S + cs0 + 4];
#pragma unroll
            for (int r = 0; r < 4; r++)
#pragma unroll
                for (int c = 0; c < 8; c++) s[r][c] += a[r] * b[c];
        }
#pragma unroll
        for (int r = 0; r < 4; r++)
#pragma unroll
            for (int c = 0; c < 8; c++)
                s[r][c] = __expf(s[r][c] * 0.1f - mv[cs0 + c]);

        __syncthreads();   // all K reads done before E overwrites the region
#pragma unroll
        for (int r = 0; r < 4; r++) {
            *(float4*)&KE[(rq0 + r) * KT_S + cs0]     = *(float4*)&s[r][0];
            *(float4*)&KE[(rq0 + r) * KT_S + cs0 + 4] = *(float4*)&s[r][4];
        }
        __syncthreads();

        // PV: 4 q x 4 d per thread, k blocked by 4 (E reads are LDS.128)
#pragma unroll 4
        for (int k4 = 0; k4 < 128; k4 += 4) {
            float e[4][4];
#pragma unroll
            for (int r = 0; r < 4; r++)
                *(float4*)&e[r][0] = *(const float4*)&KE[(rq0 + r) * KT_S + k4];
#pragma unroll
            for (int j = 0; j < 4; j++) {
                float4 vv = *(const float4*)&Vs[(k4 + j) * QT_S + cp0];
#pragma unroll
                for (int r = 0; r < 4; r++) {
                    o[r][0] += e[r][j] * vv.x;
                    o[r][1] += e[r][j] * vv.y;
                    o[r][2] += e[r][j] * vv.z;
                    o[r][3] += e[r][j] * vv.w;
                }
            }
        }
    }

    const int b = bh >> 4, h = bh & 15;
#pragma unroll
    for (int r = 0; r < 4; r++) {
        int q = q0 + rq0 + r;
        *(float4*)(out + ((size_t)(b * SEQ + q)) * EMBED + h * DH + cp0) =
            make_float4(o[r][0], o[r][1], o[r][2], o[r][3]);
    }
}

// ---------------------------------------------------------------------------
extern "C" void kernel_launch(void* const* d_in, const int* in_sizes, int n_in,
                              void* d_out, int out_size)
{
    const float* x  = (const float*)d_in[0];
    const float* Wq = (const float*)d_in[1];
    const float* bq = (const float*)d_in[2];
    const float* Wk = (const float*)d_in[3];
    const float* bk = (const float*)d_in[4];
    const float* Wv = (const float*)d_in[5];
    const float* bv = (const float*)d_in[6];
    float* out = (float*)d_out;

    float *pQ, *pK, *pV, *pM, *pIC;
    cudaGetSymbolAddress((void**)&pQ,  g_Q);
    cudaGetSymbolAddress((void**)&pK,  g_K);
    cudaGetSymbolAddress((void**)&pV,  g_V);
    cudaGetSymbolAddress((void**)&pM,  g_M);
    cudaGetSymbolAddress((void**)&pIC, g_IC);

    dim3 pg(EMBED / 128, (BATCH * SEQ) / 128);   // (8, 64)
    proj_kernel<<<pg, 256>>>(x, Wq, bq, pQ);
    proj_kernel<<<pg, 256>>>(x, Wk, bk, pK);
    proj_kernel<<<pg, 256>>>(x, Wv, bv, pV);

    const int stats_smem = (2 * 64 * KT_S + 2 * 128 * 16) * (int)sizeof(float); // 83968
    cudaFuncSetAttribute(stats_kernel, cudaFuncAttributeMaxDynamicSharedMemorySize, stats_smem);
    dim3 sg(SEQ / 128, BH);                       // (16, 64)
    stats_kernel<<<sg, 256, stats_smem>>>(pM, pIC);

    const int attn_smem = (64 * QT_S + 64 * KT_S + 128 * QT_S + 128) * (int)sizeof(float); // 86528
    cudaFuncSetAttribute(attn_kernel, cudaFuncAttributeMaxDynamicSharedMemorySize, attn_smem);
    dim3 ag(SEQ / 64, BH);                        // (32, 64)
    attn_kernel<<<ag, 256, attn_smem>>>(out, pM, pIC);
}

// round 4
// speedup vs baseline: 1.3763x; 1.2909x over previous
#include <cuda_runtime.h>
#include <cuda_bf16.h>
#include <math.h>
#include <cstdint>

#define BATCH 4
#define SEQ   2048
#define EMBED 1024
#define HEADS 16
#define DH    64
#define BH    (BATCH*HEADS)   // 64

__device__ float g_Q[(size_t)BH*SEQ*DH];
__device__ float g_K[(size_t)BH*SEQ*DH];
__device__ float g_V[(size_t)BH*SEQ*DH];
__device__ float g_M [(size_t)BH*SEQ];
__device__ float g_IC[(size_t)BH*SEQ];

// bf16 split copies of x and W's
__device__ __nv_bfloat16 g_xhi[(size_t)BATCH*SEQ*EMBED];
__device__ __nv_bfloat16 g_xlo[(size_t)BATCH*SEQ*EMBED];
__device__ __nv_bfloat16 g_whi[(size_t)3*EMBED*EMBED];
__device__ __nv_bfloat16 g_wlo[(size_t)3*EMBED*EMBED];

__device__ __forceinline__ uint32_t smem_u32(const void* p) {
    uint32_t a;
    asm("{ .reg .u64 t; cvta.to.shared.u64 t, %1; cvt.u32.u64 %0, t; }" : "=r"(a) : "l"(p));
    return a;
}
__device__ __forceinline__ void ldsm4(uint32_t (&r)[4], uint32_t addr) {
    asm volatile("ldmatrix.sync.aligned.m8n8.x4.shared.b16 {%0,%1,%2,%3}, [%4];"
                 : "=r"(r[0]), "=r"(r[1]), "=r"(r[2]), "=r"(r[3]) : "r"(addr));
}
__device__ __forceinline__ void mma16816(float (&c)[4], const uint32_t (&a)[4],
                                         uint32_t b0, uint32_t b1) {
    asm volatile("mma.sync.aligned.m16n8k16.row.col.f32.bf16.bf16.f32 "
                 "{%0,%1,%2,%3},{%4,%5,%6,%7},{%8,%9},{%0,%1,%2,%3};"
                 : "+f"(c[0]), "+f"(c[1]), "+f"(c[2]), "+f"(c[3])
                 : "r"(a[0]), "r"(a[1]), "r"(a[2]), "r"(a[3]), "r"(b0), "r"(b1));
}

// ---------------------------------------------------------------------------
// Split pass: fp32 -> (bf16 hi, bf16 lo) arrays.
// ---------------------------------------------------------------------------
__global__ __launch_bounds__(256) void split_kernel(
    const float4* __restrict__ in, uint2* __restrict__ hi, uint2* __restrict__ lo, int n4)
{
    int i = blockIdx.x * 256 + threadIdx.x;
    if (i >= n4) return;
    float4 v = in[i];
    __nv_bfloat16 hx = __float2bfloat16(v.x), hy = __float2bfloat16(v.y);
    __nv_bfloat16 hz = __float2bfloat16(v.z), hw = __float2bfloat16(v.w);
    __nv_bfloat16 lx = __float2bfloat16(v.x - __bfloat162float(hx));
    __nv_bfloat16 ly = __float2bfloat16(v.y - __bfloat162float(hy));
    __nv_bfloat16 lz = __float2bfloat16(v.z - __bfloat162float(hz));
    __nv_bfloat16 lw = __float2bfloat16(v.w - __bfloat162float(hw));
    uint2 h, l;
    h.x = (uint32_t)__bfloat16_as_ushort(hx) | ((uint32_t)__bfloat16_as_ushort(hy) << 16);
    h.y = (uint32_t)__bfloat16_as_ushort(hz) | ((uint32_t)__bfloat16_as_ushort(hw) << 16);
    l.x = (uint32_t)__bfloat16_as_ushort(lx) | ((uint32_t)__bfloat16_as_ushort(ly) << 16);
    l.y = (uint32_t)__bfloat16_as_ushort(lz) | ((uint32_t)__bfloat16_as_ushort(lw) << 16);
    hi[i] = h;
    lo[i] = l;
}

// ---------------------------------------------------------------------------
// Pass A (tensor): y = x @ W^T + bias via bf16-split mma.sync.
// 128x128 CTA tile, k-chunk 64. Warp grid 4(m) x 2(n); warp tile 32x64.
// ---------------------------------------------------------------------------
#define AST 72                         // smem row stride in bf16 (144 B)
#define TILE_B (128 * AST * 2)         // 18432 B per matrix
#define PROJ_SMEM (4 * TILE_B)         // 73728 B

__global__ __launch_bounds__(256) void proj_mma_kernel(
    const __nv_bfloat16* __restrict__ Ahi, const __nv_bfloat16* __restrict__ Alo,
    const __nv_bfloat16* __restrict__ Bhi, const __nv_bfloat16* __restrict__ Blo,
    const float* __restrict__ bias, float* __restrict__ outp)
{
    extern __shared__ char smem[];
    const uint32_t sbase = smem_u32(smem);
    const uint32_t sAhi = sbase;
    const uint32_t sAlo = sbase + TILE_B;
    const uint32_t sBhi = sbase + 2 * TILE_B;
    const uint32_t sBlo = sbase + 3 * TILE_B;

    const int tid  = threadIdx.x;
    const int wid  = tid >> 5;
    const int lane = tid & 31;
    const int m0 = blockIdx.y * 128;
    const int n0 = blockIdx.x * 128;
    const int wm = (wid & 3) * 32;     // warp m offset
    const int wn = (wid >> 2) * 64;    // warp n offset

    float acc[16][4];
#pragma unroll
    for (int t = 0; t < 16; t++)
#pragma unroll
        for (int e = 0; e < 4; e++) acc[t][e] = 0.f;

    for (int kc = 0; kc < 16; kc++) {
        const int k0 = kc * 64;
        __syncthreads();
        // load 128x64 bf16 tiles for all 4 matrices; 16B chunks, coalesced rows
#pragma unroll
        for (int t = 0; t < 4; t++) {
            int i = tid + t * 256;         // 0..1023
            int c = i & 7;                 // 16B chunk within row (8 chunks)
            int r = i >> 3;                // row 0..127
            size_t goffA = (size_t)(m0 + r) * EMBED + k0 + c * 8;
            size_t goffB = (size_t)(n0 + r) * EMBED + k0 + c * 8;
            uint32_t soff = (uint32_t)(r * AST + c * 8) * 2;
            *(uint4*)(smem + (sAhi - sbase) + soff) = *(const uint4*)(Ahi + goffA);
            *(uint4*)(smem + (sAlo - sbase) + soff) = *(const uint4*)(Alo + goffA);
            *(uint4*)(smem + (sBhi - sbase) + soff) = *(const uint4*)(Bhi + goffB);
            *(uint4*)(smem + (sBlo - sbase) + soff) = *(const uint4*)(Blo + goffB);
        }
        __syncthreads();

#pragma unroll
        for (int s = 0; s < 4; s++) {           // k16 steps
            const uint32_t colb = (uint32_t)(s * 32 + (lane >> 4) * 16);
            const uint32_t arow = (uint32_t)(wm + (lane & 15)) * (AST * 2);
            uint32_t ahi[2][4], alo[2][4];
#pragma unroll
            for (int i = 0; i < 2; i++) {
                ldsm4(ahi[i], sAhi + arow + i * 16 * AST * 2 + colb);
                ldsm4(alo[i], sAlo + arow + i * 16 * AST * 2 + colb);
            }
#pragma unroll
            for (int j4 = 0; j4 < 4; j4++) {    // pairs of n8 tiles
                const uint32_t brow = (uint32_t)(wn + j4 * 16 + (lane & 15)) * (AST * 2);
                uint32_t bhi[4], blo[4];
                ldsm4(bhi, sBhi + brow + colb);
                ldsm4(blo, sBlo + brow + colb);
#pragma unroll
                for (int i = 0; i < 2; i++)
#pragma unroll
                    for (int o = 0; o < 2; o++) {
                        float (&cc)[4] = acc[i * 8 + j4 * 2 + o];
                        mma16816(cc, ahi[i], bhi[o], bhi[o + 2]);
                        mma16816(cc, ahi[i], blo[o], blo[o + 2]);
                        mma16816(cc, alo[i], bhi[o], bhi[o + 2]);
                    }
            }
        }
    }

    // epilogue: bias + [b][h][s][d] remap, direct float2 stores
#pragma unroll
    for (int i = 0; i < 2; i++) {
        int mrow = m0 + wm + 16 * i + (lane >> 2);
#pragma unroll
        for (int j = 0; j < 8; j++) {
            int n = n0 + wn + 8 * j + (lane & 3) * 2;
            int h = n >> 6, d = n & 63;
            float2 bb = *(const float2*)(bias + n);
            float* base = outp + ((size_t)((mrow >> 11) * HEADS + h) * SEQ) * DH + d;
            int s0 = mrow & 2047;
            *(float2*)(base + (size_t)s0 * DH) =
                make_float2(acc[i * 8 + j][0] + bb.x, acc[i * 8 + j][1] + bb.y);
            int m2 = mrow + 8;
            float* base2 = outp + ((size_t)((m2 >> 11) * HEADS + h) * SEQ) * DH + d;
            *(float2*)(base2 + (size_t)(m2 & 2047) * DH) =
                make_float2(acc[i * 8 + j][2] + bb.x, acc[i * 8 + j][3] + bb.y);
        }
    }
}

// ---------------------------------------------------------------------------
// Pass B: per (bh, k): m_k = max_q S, den_k = sum_q exp(S-m_k).  (unchanged)
// ---------------------------------------------------------------------------
#define KT_S 132
__global__ __launch_bounds__(256, 2) void stats_kernel(
    float* __restrict__ gM, float* __restrict__ gIC)
{
    extern __shared__ float sm[];
    float* Ks   = sm;
    float* Qs   = sm + 64 * KT_S;
    float* redm = sm + 2 * 64 * KT_S;
    float* redd = redm + 128 * 16;

    const int tid = threadIdx.x;
    const int bh = blockIdx.y;
    const int k0 = blockIdx.x * 128;
    const int tx = tid & 15, ty = tid >> 4;
    const int c0 = tx * 8, r0 = ty * 8;

    const float* Kp = g_K + ((size_t)bh * SEQ + k0) * DH;
    for (int i = tid; i < 128 * 16; i += 256) {
        int row = i >> 4, c4 = (i & 15) << 2;
        float4 v = *(const float4*)(Kp + (size_t)row * DH + c4);
        Ks[(c4 + 0) * KT_S + row] = v.x; Ks[(c4 + 1) * KT_S + row] = v.y;
        Ks[(c4 + 2) * KT_S + row] = v.z; Ks[(c4 + 3) * KT_S + row] = v.w;
    }
    const float* Qp = g_Q + (size_t)bh * SEQ * DH;

    float rm[8], rd[8];
#pragma unroll
    for (int c = 0; c < 8; c++) { rm[c] = -1e30f; rd[c] = 0.f; }

    for (int q0 = 0; q0 < SEQ; q0 += 128) {
        __syncthreads();
        for (int i = tid; i < 128 * 16; i += 256) {
            int row = i >> 4, c4 = (i & 15) << 2;
            float4 v = *(const float4*)(Qp + (size_t)(q0 + row) * DH + c4);
            Qs[(c4 + 0) * KT_S + row] = v.x; Qs[(c4 + 1) * KT_S + row] = v.y;
            Qs[(c4 + 2) * KT_S + row] = v.z; Qs[(c4 + 3) * KT_S + row] = v.w;
        }
        __syncthreads();

        float acc[8][8];
#pragma unroll
        for (int r = 0; r < 8; r++)
#pragma unroll
            for (int c = 0; c < 8; c++) acc[r][c] = 0.f;

#pragma unroll 8
        for (int d = 0; d < DH; d++) {
            float a[8], b[8];
            *(float4*)&a[0] = *(const float4*)&Qs[d * KT_S + r0];
            *(float4*)&a[4] = *(const float4*)&Qs[d * KT_S + r0 + 4];
            *(float4*)&b[0] = *(const float4*)&Ks[d * KT_S + c0];
            *(float4*)&b[4] = *(const float4*)&Ks[d * KT_S + c0 + 4];
#pragma unroll
            for (int r = 0; r < 8; r++)
#pragma unroll
                for (int c = 0; c < 8; c++) acc[r][c] += a[r] * b[c];
        }

#pragma unroll
        for (int c = 0; c < 8; c++) {
            float tm = acc[0][c];
#pragma unroll
            for (int r = 1; r < 8; r++) tm = fmaxf(tm, acc[r][c]);
            tm *= 0.1f;
            if (tm > rm[c]) { rd[c] *= __expf(rm[c] - tm); rm[c] = tm; }
#pragma unroll
            for (int r = 0; r < 8; r++) rd[c] += __expf(acc[r][c] * 0.1f - rm[c]);
        }
    }

#pragma unroll
    for (int c = 0; c < 8; c++) {
        redm[(c0 + c) * 16 + ty] = rm[c];
        redd[(c0 + c) * 16 + ty] = rd[c];
    }
    __syncthreads();
    if (tid < 128) {
        float M = -1e30f;
#pragma unroll
        for (int i = 0; i < 16; i++) M = fmaxf(M, redm[tid * 16 + i]);
        float D = 0.f;
#pragma unroll
        for (int i = 0; i < 16; i++) D += redd[tid * 16 + i] * __expf(redm[tid * 16 + i] - M);
        gM [(size_t)bh * SEQ + k0 + tid] = M;
        gIC[(size_t)bh * SEQ + k0 + tid] = 1.0f / D;
    }
}

// ---------------------------------------------------------------------------
// Pass C: O[q,d] = sum_k exp(S-m_k) * (V[k,d]/den_k).  (unchanged)
// ---------------------------------------------------------------------------
#define QT_S 68
__global__ __launch_bounds__(256, 2) void attn_kernel(
    float* __restrict__ out,
    const float* __restrict__ gM, const float* __restrict__ gIC)
{
    extern __shared__ float sm[];
    float* Qs = sm;
    float* KE = sm + 64 * QT_S;
    float* Vs = KE + 64 * KT_S;
    float* mv = Vs + 128 * QT_S;

    const int tid = threadIdx.x;
    const int bh = blockIdx.y;
    const int q0 = blockIdx.x * 64;
    const int tx = tid & 15, ty = tid >> 4;
    const int cs0 = tx * 8;
    const int rq0 = ty * 4;
    const int cp0 = tx * 4;

    const float* Qp = g_Q + ((size_t)bh * SEQ + q0) * DH;
    for (int i = tid; i < 64 * 16; i += 256) {
        int row = i >> 4, c4 = (i & 15) << 2;
        float4 v = *(const float4*)(Qp + (size_t)row * DH + c4);
        Qs[(c4 + 0) * QT_S + row] = v.x; Qs[(c4 + 1) * QT_S + row] = v.y;
        Qs[(c4 + 2) * QT_S + row] = v.z; Qs[(c4 + 3) * QT_S + row] = v.w;
    }

    float o[4][4];
#pragma unroll
    for (int r = 0; r < 4; r++)
#pragma unroll
        for (int c = 0; c < 4; c++) o[r][c] = 0.f;

    for (int k0 = 0; k0 < SEQ; k0 += 128) {
        __syncthreads();
        const float* Kp  = g_K + ((size_t)bh * SEQ + k0) * DH;
        const float* Vp  = g_V + ((size_t)bh * SEQ + k0) * DH;
        const float* icp = gIC + (size_t)bh * SEQ + k0;
        for (int i = tid; i < 128 * 16; i += 256) {
            int row = i >> 4, c4 = (i & 15) << 2;
            float4 kv = *(const float4*)(Kp + (size_t)row * DH + c4);
            KE[(c4 + 0) * KT_S + row] = kv.x; KE[(c4 + 1) * KT_S + row] = kv.y;
            KE[(c4 + 2) * KT_S + row] = kv.z; KE[(c4 + 3) * KT_S + row] = kv.w;
            float ic = icp[row];
            float4 vv = *(const float4*)(Vp + (size_t)row * DH + c4);
            *(float4*)&Vs[row * QT_S + c4] =
                make_float4(vv.x * ic, vv.y * ic, vv.z * ic, vv.w * ic);
        }
        if (tid < 128) mv[tid] = gM[(size_t)bh * SEQ + k0 + tid];
        __syncthreads();

        float s[4][8];
#pragma unroll
        for (int r = 0; r < 4; r++)
#pragma unroll
            for (int c = 0; c < 8; c++) s[r][c] = 0.f;
#pragma unroll 8
        for (int d = 0; d < DH; d++) {
            float a[4], b[8];
            *(float4*)&a[0] = *(const float4*)&Qs[d * QT_S + rq0];
            *(float4*)&b[0] = *(const float4*)&KE[d * KT_S + cs0];
            *(float4*)&b[4] = *(const float4*)&KE[d * KT_S + cs0 + 4];
#pragma unroll
            for (int r = 0; r < 4; r++)
#pragma unroll
                for (int c = 0; c < 8; c++) s[r][c] += a[r] * b[c];
        }
#pragma unroll
        for (int r = 0; r < 4; r++)
#pragma unroll
            for (int c = 0; c < 8; c++)
                s[r][c] = __expf(s[r][c] * 0.1f - mv[cs0 + c]);

        __syncthreads();
#pragma unroll
        for (int r = 0; r < 4; r++) {
            *(float4*)&KE[(rq0 + r) * KT_S + cs0]     = *(float4*)&s[r][0];
            *(float4*)&KE[(rq0 + r) * KT_S + cs0 + 4] = *(float4*)&s[r][4];
        }
        __syncthreads();

#pragma unroll 4
        for (int k4 = 0; k4 < 128; k4 += 4) {
            float e[4][4];
#pragma unroll
            for (int r = 0; r < 4; r++)
                *(float4*)&e[r][0] = *(const float4*)&KE[(rq0 + r) * KT_S + k4];
#pragma unroll
            for (int j = 0; j < 4; j++) {
                float4 vv = *(const float4*)&Vs[(k4 + j) * QT_S + cp0];
#pragma unroll
                for (int r = 0; r < 4; r++) {
                    o[r][0] += e[r][j] * vv.x;
                    o[r][1] += e[r][j] * vv.y;
                    o[r][2] += e[r][j] * vv.z;
                    o[r][3] += e[r][j] * vv.w;
                }
            }
        }
    }

    const int b = bh >> 4, h = bh & 15;
#pragma unroll
    for (int r = 0; r < 4; r++) {
        int q = q0 + rq0 + r;
        *(float4*)(out + ((size_t)(b * SEQ + q)) * EMBED + h * DH + cp0) =
            make_float4(o[r][0], o[r][1], o[r][2], o[r][3]);
    }
}

// ---------------------------------------------------------------------------
extern "C" void kernel_launch(void* const* d_in, const int* in_sizes, int n_in,
                              void* d_out, int out_size)
{
    const float* x  = (const float*)d_in[0];
    const float* Wq = (const float*)d_in[1];
    const float* bq = (const float*)d_in[2];
    const float* Wk = (const float*)d_in[3];
    const float* bk = (const float*)d_in[4];
    const float* Wv = (const float*)d_in[5];
    const float* bv = (const float*)d_in[6];
    float* out = (float*)d_out;

    float *pQ, *pK, *pV, *pM, *pIC;
    __nv_bfloat16 *pxh, *pxl, *pwh, *pwl;
    cudaGetSymbolAddress((void**)&pQ,  g_Q);
    cudaGetSymbolAddress((void**)&pK,  g_K);
    cudaGetSymbolAddress((void**)&pV,  g_V);
    cudaGetSymbolAddress((void**)&pM,  g_M);
    cudaGetSymbolAddress((void**)&pIC, g_IC);
    cudaGetSymbolAddress((void**)&pxh, g_xhi);
    cudaGetSymbolAddress((void**)&pxl, g_xlo);
    cudaGetSymbolAddress((void**)&pwh, g_whi);
    cudaGetSymbolAddress((void**)&pwl, g_wlo);

    const int xn4 = BATCH * SEQ * EMBED / 4;       // 2097152
    const int wn4 = EMBED * EMBED / 4;             // 262144
    split_kernel<<<(xn4 + 255) / 256, 256>>>((const float4*)x,  (uint2*)pxh, (uint2*)pxl, xn4);
    split_kernel<<<(wn4 + 255) / 256, 256>>>((const float4*)Wq, (uint2*)(pwh),                 (uint2*)(pwl),                 wn4);
    split_kernel<<<(wn4 + 255) / 256, 256>>>((const float4*)Wk, (uint2*)(pwh + (size_t)EMBED*EMBED),   (uint2*)(pwl + (size_t)EMBED*EMBED),   wn4);
    split_kernel<<<(wn4 + 255) / 256, 256>>>((const float4*)Wv, (uint2*)(pwh + (size_t)2*EMBED*EMBED), (uint2*)(pwl + (size_t)2*EMBED*EMBED), wn4);

    cudaFuncSetAttribute(proj_mma_kernel, cudaFuncAttributeMaxDynamicSharedMemorySize, PROJ_SMEM);
    dim3 pg(EMBED / 128, (BATCH * SEQ) / 128);     // (8, 64)
    proj_mma_kernel<<<pg, 256, PROJ_SMEM>>>(pxh, pxl, pwh, pwl, bq, pQ);
    proj_mma_kernel<<<pg, 256, PROJ_SMEM>>>(pxh, pxl, pwh + (size_t)EMBED*EMBED,   pwl + (size_t)EMBED*EMBED,   bk, pK);
    proj_mma_kernel<<<pg, 256, PROJ_SMEM>>>(pxh, pxl, pwh + (size_t)2*EMBED*EMBED, pwl + (size_t)2*EMBED*EMBED, bv, pV);

    const int stats_smem = (2 * 64 * KT_S + 2 * 128 * 16) * (int)sizeof(float);
    cudaFuncSetAttribute(stats_kernel, cudaFuncAttributeMaxDynamicSharedMemorySize, stats_smem);
    dim3 sg(SEQ / 128, BH);                        // (16, 64)
    stats_kernel<<<sg, 256, stats_smem>>>(pM, pIC);

    const int attn_smem = (64 * QT_S + 64 * KT_S + 128 * QT_S + 128) * (int)sizeof(float);
    cudaFuncSetAttribute(attn_kernel, cudaFuncAttributeMaxDynamicSharedMemorySize, attn_smem);
    dim3 ag(SEQ / 64, BH);                         // (32, 64)
    attn_kernel<<<ag, 256, attn_smem>>>(out, pM, pIC);
}